// round 5
// baseline (speedup 1.0000x reference)
#include <cuda_runtime.h>
#include <math.h>

#define F_LEN 1000.0f
#define IMG   512.0f
#define EPSF  1e-8f
#define EPSD  1e-8

// acc slots: 0 shape, 1 pose, 2 betas, 3 n_valid, 4 kp23(combined), 6 pa
// Zero at module load; finalize block re-zeroes after use (graph-replay safe).
__device__ struct {
    double acc[7];
    unsigned int done;
    unsigned int pad;
} g_state;

__device__ __forceinline__ float wsum(float v) {
    #pragma unroll
    for (int o = 16; o; o >>= 1) v += __shfl_xor_sync(0xffffffffu, v, o);
    return v;
}

__device__ __forceinline__ void block_reduce_add(float local, double* slot,
                                                 double* sh)
{
    double v = (double)local;
    #pragma unroll
    for (int o = 16; o; o >>= 1) v += __shfl_down_sync(0xffffffffu, v, o);
    int lane = threadIdx.x & 31, wid = threadIdx.x >> 5;
    if (lane == 0) sh[wid] = v;
    __syncthreads();
    if (wid == 0) {
        int nw = blockDim.x >> 5;
        v = (lane < nw) ? sh[lane] : 0.0;
        #pragma unroll
        for (int o = 16; o; o >>= 1) v += __shfl_down_sync(0xffffffffu, v, o);
        if (lane == 0) atomicAdd(slot, v);
    }
    __syncthreads();
}

// ---------------------------------------------------------------------------
__global__ __launch_bounds__(256, 5)
void fused_kernel(const float* __restrict__ pred_rotmat,
                  const float* __restrict__ pred_camera,
                  const float* __restrict__ pred_joints,
                  const float* __restrict__ pred_vertices,
                  const float* __restrict__ pred_betas,
                  const float* __restrict__ gt_rotmat,
                  const float* __restrict__ gt_shape,
                  const float* __restrict__ gt_kp2d,
                  const float* __restrict__ gt_kp3d,
                  const float* __restrict__ gt_vertices,
                  const int*   __restrict__ has_smpl,
                  int B, int V, int batchBlocks,
                  unsigned long long magic,
                  float* __restrict__ out)
{
    __shared__ double sh[32];
    __shared__ float smask[2048];
    const unsigned FM = 0xffffffffu;
    const int per_batch = V * 3;
    const int ntot = B * per_batch;
    const int n4 = ntot / 4;

    if (blockIdx.x >= batchBlocks) {
        // ============ vertex L1 + pose L2 — load ONLY masked-in batches ======
        const int vblocks = gridDim.x - batchBlocks;
        const int vbid = blockIdx.x - batchBlocks;
        const float4* pv4 = reinterpret_cast<const float4*>(pred_vertices);
        const float4* gv4 = reinterpret_cast<const float4*>(gt_vertices);

        for (int i = threadIdx.x; i < 2048; i += blockDim.x)
            smask[i] = (i < B && __ldg(has_smpl + i) > 0) ? 1.0f : 0.0f;
        __syncthreads();

        const int stride = vblocks * blockDim.x;
        int base = vbid * blockDim.x + threadIdx.x;
        float lshape = 0.0f;

        int i = base;
        for (; i + 3 * stride < n4; i += 4 * stride) {
            int   idx[4];
            float mm[4];
            bool  take[4], cross[4];
            #pragma unroll
            for (int u = 0; u < 4; u++) {
                idx[u] = i + u * stride;
                int e = idx[u] * 4;
                unsigned int b0 = (unsigned int)(((unsigned long long)(unsigned int)e * magic) >> 40);
                int r = e - (int)b0 * per_batch;
                cross[u] = (r + 3 >= per_batch);
                float m0 = smask[b0 & 2047];
                float m1 = cross[u] ? smask[(b0 + 1) & 2047] : 0.0f;
                mm[u]   = m0;
                take[u] = (m0 != 0.0f) || (cross[u] && m1 != 0.0f);
            }
            // issue all surviving loads back-to-back (predicated, no branch)
            float4 aa[4], cc[4];
            #pragma unroll
            for (int u = 0; u < 4; u++) {
                if (take[u]) { aa[u] = __ldg(pv4 + idx[u]); cc[u] = __ldg(gv4 + idx[u]); }
            }
            #pragma unroll
            for (int u = 0; u < 4; u++) {
                if (!take[u]) continue;
                float d0 = fabsf(aa[u].x - cc[u].x);
                float d1 = fabsf(aa[u].y - cc[u].y);
                float d2 = fabsf(aa[u].z - cc[u].z);
                float d3 = fabsf(aa[u].w - cc[u].w);
                if (!cross[u]) {
                    lshape += mm[u] * (d0 + d1 + d2 + d3);
                } else {
                    int e = idx[u] * 4;
                    float d[4] = {d0, d1, d2, d3};
                    #pragma unroll
                    for (int k = 0; k < 4; k++) {
                        unsigned int bb = (unsigned int)(((unsigned long long)(unsigned int)(e + k) * magic) >> 40);
                        lshape += smask[bb & 2047] * d[k];
                    }
                }
            }
        }
        for (; i < n4; i += stride) {
            int e = i * 4;
            unsigned int b0 = (unsigned int)(((unsigned long long)(unsigned int)e * magic) >> 40);
            int r = e - (int)b0 * per_batch;
            bool cross = (r + 3 >= per_batch);
            float m0 = smask[b0 & 2047];
            float m1 = cross ? smask[(b0 + 1) & 2047] : 0.0f;
            if (m0 == 0.0f && !(cross && m1 != 0.0f)) continue;
            float4 a = __ldg(pv4 + i);
            float4 c = __ldg(gv4 + i);
            float d0 = fabsf(a.x - c.x), d1 = fabsf(a.y - c.y);
            float d2 = fabsf(a.z - c.z), d3 = fabsf(a.w - c.w);
            if (!cross) {
                lshape += m0 * (d0 + d1 + d2 + d3);
            } else {
                float d[4] = {d0, d1, d2, d3};
                #pragma unroll
                for (int k = 0; k < 4; k++) {
                    unsigned int bb = (unsigned int)(((unsigned long long)(unsigned int)(e + k) * magic) >> 40);
                    lshape += smask[bb & 2047] * d[k];
                }
            }
        }
        if (vbid == 0 && threadIdx.x == 0) {
            for (int e = n4 * 4; e < ntot; ++e) {
                int bb = e / per_batch;
                float m = (__ldg(has_smpl + bb) > 0) ? 1.0f : 0.0f;
                if (m != 0.0f)
                    lshape += m * fabsf(__ldg(pred_vertices + e) - __ldg(gt_vertices + e));
            }
        }

        // pose loss: 54 float4 per batch, skip masked-out batches
        float lpose = 0.0f;
        {
            const float4* pr4 = reinterpret_cast<const float4*>(pred_rotmat);
            const float4* gr4 = reinterpret_cast<const float4*>(gt_rotmat);
            int n4p = B * 54;
            for (int j = base; j < n4p; j += stride) {
                int b0 = j / 54;                 // constant divisor
                float m = smask[b0 & 2047];
                if (m == 0.0f) continue;
                float4 a = __ldg(pr4 + j);
                float4 b = __ldg(gr4 + j);
                float d0 = a.x - b.x, d1 = a.y - b.y, d2 = a.z - b.z, d3 = a.w - b.w;
                lpose += d0*d0 + d1*d1 + d2*d2 + d3*d3;   // m==1 here
            }
        }

        block_reduce_add(lshape, &g_state.acc[0], sh);
        block_reduce_add(lpose,  &g_state.acc[1], sh);
    } else {
        // ================= per-batch losses (warp per batch) =================
        int gw   = (blockIdx.x * blockDim.x + threadIdx.x) >> 5;
        int lane = threadIdx.x & 31;

        if (gw < B) {
            const int b = gw;
            const bool act = (lane < 24);

            float px = 0.f, py = 0.f, pz = 0.f;
            float gx = 0.f, gy = 0.f, gz = 0.f, c3 = 0.f;
            float g2x = 0.f, g2y = 0.f, c2 = 0.f;
            if (act) {
                const float* pj = pred_joints + ((size_t)b * 24 + lane) * 3;
                px = __ldg(pj + 0); py = __ldg(pj + 1); pz = __ldg(pj + 2);
                const float* gk = gt_kp3d + ((size_t)b * 24 + lane) * 4;
                gx = __ldg(gk + 0); gy = __ldg(gk + 1); gz = __ldg(gk + 2); c3 = __ldg(gk + 3);
                const float* g2 = gt_kp2d + ((size_t)b * 24 + lane) * 3;
                g2x = __ldg(g2 + 0); g2y = __ldg(g2 + 1); c2 = __ldg(g2 + 2);
            }
            float cam0 = __ldg(pred_camera + b * 3 + 0);
            float cam1 = __ldg(pred_camera + b * 3 + 1);
            float cam2 = __ldg(pred_camera + b * 3 + 2);

            // ---- kp2d ----
            float s2 = 0.f;
            {
                float depth = __fdividef(2.0f * F_LEN, EPSF + cam0 * IMG);
                if (act) {
                    float invz = __fdividef(1.0f, pz + depth);
                    float kx = (F_LEN * (px + cam1) * invz + IMG * 0.5f) * (1.0f / IMG);
                    float ky = (F_LEN * (py + cam2) * invz + IMG * 0.5f) * (1.0f / IMG);
                    s2 = c2 * (fabsf(kx - g2x * (1.0f / IMG)) +
                               fabsf(ky - g2y * (1.0f / IMG)));
                }
            }

            // ---- kp3d ----
            float ppx = 0.5f * (__shfl_sync(FM, px, 2) + __shfl_sync(FM, px, 3));
            float ppy = 0.5f * (__shfl_sync(FM, py, 2) + __shfl_sync(FM, py, 3));
            float ppz = 0.5f * (__shfl_sync(FM, pz, 2) + __shfl_sync(FM, pz, 3));
            float gpx = 0.5f * (__shfl_sync(FM, gx, 2) + __shfl_sync(FM, gx, 3));
            float gpy = 0.5f * (__shfl_sync(FM, gy, 2) + __shfl_sync(FM, gy, 3));
            float gpz = 0.5f * (__shfl_sync(FM, gz, 2) + __shfl_sync(FM, gz, 3));
            float s3 = 0.f;
            if (act) {
                s3 = c3 * (fabsf((px - ppx) - (gx - gpx)) +
                           fabsf((py - ppy) - (gy - gpy)) +
                           fabsf((pz - ppz) - (gz - gpz)));
            }
            float s23 = wsum(s2 * (1.0f / 48.0f) + s3 * (1.0f / 72.0f));

            // ---- betas ----
            float m = (__ldg(has_smpl + b) > 0) ? 1.0f : 0.0f;
            float sb = 0.f;
            if (lane < 10) {
                float d = __ldg(pred_betas + b * 10 + lane) - __ldg(gt_shape + b * 10 + lane);
                sb = d * d;
            }
            sb = wsum(sb) * m;

            // ---- Procrustes (fp32, per-warp) ----
            const float inv24 = 1.0f / 24.0f;
            float m1x = wsum(px) * inv24, m1y = wsum(py) * inv24, m1z = wsum(pz) * inv24;
            float m2x = wsum(gx) * inv24, m2y = wsum(gy) * inv24, m2z = wsum(gz) * inv24;

            float x1x = 0.f, x1y = 0.f, x1z = 0.f, x2x = 0.f, x2y = 0.f, x2z = 0.f;
            if (act) {
                x1x = px - m1x; x1y = py - m1y; x1z = pz - m1z;
                x2x = gx - m2x; x2y = gy - m2y; x2z = gz - m2z;
            }
            float var1 = wsum(x1x * x1x + x1y * x1y + x1z * x1z);

            float K[3][3];
            K[0][0] = wsum(x1x * x2x) + EPSF; K[0][1] = wsum(x1x * x2y) + EPSF; K[0][2] = wsum(x1x * x2z) + EPSF;
            K[1][0] = wsum(x1y * x2x) + EPSF; K[1][1] = wsum(x1y * x2y) + EPSF; K[1][2] = wsum(x1y * x2z) + EPSF;
            K[2][0] = wsum(x1z * x2x) + EPSF; K[2][1] = wsum(x1z * x2y) + EPSF; K[2][2] = wsum(x1z * x2z) + EPSF;

            float A[3][3];
            #pragma unroll
            for (int r = 0; r < 3; r++)
                #pragma unroll
                for (int c = 0; c < 3; c++)
                    A[r][c] = K[0][r] * K[0][c] + K[1][r] * K[1][c] + K[2][r] * K[2][c];

            float Vv[3][3] = {{1.f,0.f,0.f},{0.f,1.f,0.f},{0.f,0.f,1.f}};
            float nrm = A[0][0]*A[0][0] + A[1][1]*A[1][1] + A[2][2]*A[2][2];
            for (int sweep = 0; sweep < 8; ++sweep) {
                float off = A[0][1]*A[0][1] + A[0][2]*A[0][2] + A[1][2]*A[1][2];
                if (off <= 1e-14f * nrm) break;
                #pragma unroll
                for (int p = 0; p < 2; p++) {
                    #pragma unroll
                    for (int q = p + 1; q < 3; q++) {
                        float apq = A[p][q];
                        if (fabsf(apq) < 1e-30f) continue;
                        float theta = __fdividef(A[q][q] - A[p][p], 2.0f * apq);
                        float w1 = theta * theta + 1.0f;
                        float sq = w1 * rsqrtf(w1);
                        float t = __fdividef(1.0f, fabsf(theta) + sq);
                        if (theta < 0.0f) t = -t;
                        float c = rsqrtf(t * t + 1.0f);
                        float s = t * c;
                        float app = A[p][p], aqq = A[q][q];
                        A[p][p] = app - t * apq;
                        A[q][q] = aqq + t * apq;
                        A[p][q] = A[q][p] = 0.0f;
                        int k = 3 - p - q;
                        float akp = A[k][p], akq = A[k][q];
                        A[k][p] = A[p][k] = c * akp - s * akq;
                        A[k][q] = A[q][k] = s * akp + c * akq;
                        #pragma unroll
                        for (int r = 0; r < 3; r++) {
                            float vrp = Vv[r][p], vrq = Vv[r][q];
                            Vv[r][p] = c * vrp - s * vrq;
                            Vv[r][q] = s * vrp + c * vrq;
                        }
                    }
                }
            }
            float w[3] = {A[0][0], A[1][1], A[2][2]};
            #pragma unroll
            for (int i = 0; i < 2; i++) {
                int mx = i;
                #pragma unroll
                for (int j2 = 1; j2 < 3; j2++) if (j2 > i && w[j2] > w[mx]) mx = j2;
                if (mx != i) {
                    float tw = w[i]; w[i] = w[mx]; w[mx] = tw;
                    #pragma unroll
                    for (int r = 0; r < 3; r++) {
                        float tv = Vv[r][i]; Vv[r][i] = Vv[r][mx]; Vv[r][mx] = tv;
                    }
                }
            }

            float detK = K[0][0]*(K[1][1]*K[2][2] - K[1][2]*K[2][1])
                       - K[0][1]*(K[1][0]*K[2][2] - K[1][2]*K[2][0])
                       + K[0][2]*(K[1][0]*K[2][1] - K[1][1]*K[2][0]);
            float sgn = (detK > 0.f) ? 1.f : ((detK < 0.f) ? -1.f : 0.f);
            float z[3] = {1.f, 1.f, sgn};

            float R[3][3] = {{0,0,0},{0,0,0},{0,0,0}};
            #pragma unroll
            for (int i = 0; i < 3; i++) {
                float kv[3];
                #pragma unroll
                for (int r = 0; r < 3; r++)
                    kv[r] = K[r][0]*Vv[0][i] + K[r][1]*Vv[1][i] + K[r][2]*Vv[2][i];
                float f = z[i] * rsqrtf(fmaxf(w[i], 1e-30f));
                #pragma unroll
                for (int r = 0; r < 3; r++)
                    #pragma unroll
                    for (int c = 0; c < 3; c++)
                        R[r][c] += f * Vv[r][i] * kv[c];
            }
            float trRK = 0.f;
            #pragma unroll
            for (int r = 0; r < 3; r++)
                #pragma unroll
                for (int c = 0; c < 3; c++) trRK += R[r][c] * K[c][r];
            float scale = __fdividef(trRK, var1);

            float tx = m2x - scale * (R[0][0]*m1x + R[0][1]*m1y + R[0][2]*m1z);
            float ty = m2y - scale * (R[1][0]*m1x + R[1][1]*m1y + R[1][2]*m1z);
            float tz = m2z - scale * (R[2][0]*m1x + R[2][1]*m1y + R[2][2]*m1z);

            float err = 0.f;
            if (act) {
                float hx = scale * (R[0][0]*px + R[0][1]*py + R[0][2]*pz) + tx - gx;
                float hy = scale * (R[1][0]*px + R[1][1]*py + R[1][2]*pz) + ty - gy;
                float hz = scale * (R[2][0]*px + R[2][1]*py + R[2][2]*pz) + tz - gz;
                float hsq = hx*hx + hy*hy + hz*hz;
                err = (hsq > 0.f) ? hsq * rsqrtf(hsq) : 0.f;
            }
            err = wsum(err);

            if (lane == 0) {
                atomicAdd(&g_state.acc[4], (double)s23);
                atomicAdd(&g_state.acc[2], (double)sb);
                atomicAdd(&g_state.acc[3], (double)m);
                atomicAdd(&g_state.acc[6], (double)err);
            }
        }
        __syncthreads();
    }

    // ================= finalize: last block to arrive =================
    __threadfence();
    if (threadIdx.x == 0) {
        unsigned old = atomicInc(&g_state.done, gridDim.x - 1);
        if (old == gridDim.x - 1) {
            __threadfence();
            volatile double* a = g_state.acc;
            double nv         = a[3];
            double loss_shape = a[0] / (nv * (double)V * 3.0 + EPSD);
            double loss_pose  = a[1] / (nv * 216.0 + EPSD);
            double loss_betas = a[2] / (nv * 10.0 + EPSD);
            double l23 = 4.0 * a[4] / (double)B;
            double pa  = a[6] / ((double)B * 24.0);
            out[0] = (float)(l23 + loss_shape + loss_pose + 0.01*loss_betas + pa);
            #pragma unroll
            for (int k = 0; k < 7; k++) g_state.acc[k] = 0.0;
        }
    }
}

// ---------------------------------------------------------------------------
extern "C" void kernel_launch(void* const* d_in, const int* in_sizes, int n_in,
                              void* d_out, int out_size)
{
    const float* pred_rotmat   = (const float*)d_in[0];
    const float* pred_camera   = (const float*)d_in[1];
    const float* pred_joints   = (const float*)d_in[2];
    const float* pred_vertices = (const float*)d_in[3];
    const float* pred_betas    = (const float*)d_in[4];
    const float* gt_rotmat     = (const float*)d_in[5];
    const float* gt_shape      = (const float*)d_in[6];
    const float* gt_kp2d       = (const float*)d_in[7];
    const float* gt_kp3d       = (const float*)d_in[8];
    const float* gt_vertices   = (const float*)d_in[9];
    const int*   has_smpl      = (const int*)d_in[10];

    int B = in_sizes[1] / 3;
    int ntot = in_sizes[3];
    int V = ntot / (B * 3);
    int per_batch = V * 3;

    unsigned long long magic = ((1ULL << 40) / (unsigned long long)per_batch) + 1ULL;

    int batchBlocks = (B * 32 + 255) / 256;     // 64 for B=512
    int grid = 148 * 5;                          // one wave at 5 blocks/SM
    if (grid <= batchBlocks) grid = batchBlocks + 148;

    fused_kernel<<<grid, 256>>>(pred_rotmat, pred_camera, pred_joints,
                                pred_vertices, pred_betas, gt_rotmat,
                                gt_shape, gt_kp2d, gt_kp3d, gt_vertices,
                                has_smpl, B, V, batchBlocks, magic,
                                (float*)d_out);
}

// round 6
// speedup vs baseline: 1.2297x; 1.2297x over previous
#include <cuda_runtime.h>
#include <math.h>

#define F_LEN 1000.0f
#define IMG   512.0f
#define EPSF  1e-8f
#define EPSD  1e-8

// acc slots: 0 shape, 1 pose, 2 betas, 3 n_valid, 4 kp23(combined), 6 pa
// Zero at module load; finalize block re-zeroes after use (graph-replay safe).
__device__ struct {
    double acc[7];
    unsigned int done;
    unsigned int pad;
} g_state;

__device__ __forceinline__ float wsum(float v) {
    #pragma unroll
    for (int o = 16; o; o >>= 1) v += __shfl_xor_sync(0xffffffffu, v, o);
    return v;
}

__device__ __forceinline__ void block_reduce_add(float local, double* slot,
                                                 double* sh)
{
    double v = (double)local;
    #pragma unroll
    for (int o = 16; o; o >>= 1) v += __shfl_down_sync(0xffffffffu, v, o);
    int lane = threadIdx.x & 31, wid = threadIdx.x >> 5;
    if (lane == 0) sh[wid] = v;
    __syncthreads();
    if (wid == 0) {
        int nw = blockDim.x >> 5;
        v = (lane < nw) ? sh[lane] : 0.0;
        #pragma unroll
        for (int o = 16; o; o >>= 1) v += __shfl_down_sync(0xffffffffu, v, o);
        if (lane == 0) atomicAdd(slot, v);
    }
}

// ---------------------------------------------------------------------------
__global__ __launch_bounds__(256, 5)
void fused_kernel(const float* __restrict__ pred_rotmat,
                  const float* __restrict__ pred_camera,
                  const float* __restrict__ pred_joints,
                  const float* __restrict__ pred_vertices,
                  const float* __restrict__ pred_betas,
                  const float* __restrict__ gt_rotmat,
                  const float* __restrict__ gt_shape,
                  const float* __restrict__ gt_kp2d,
                  const float* __restrict__ gt_kp3d,
                  const float* __restrict__ gt_vertices,
                  const int*   __restrict__ has_smpl,
                  int B, int V, int batchBlocks,
                  float* __restrict__ out)
{
    __shared__ double sh[32];
    const unsigned FM = 0xffffffffu;
    const int per_batch = V * 3;

    if (blockIdx.x >= batchBlocks) {
        // ========== vertex L1: 4 blocks per batch, block-level mask skip =====
        int v = blockIdx.x - batchBlocks;
        int b = v >> 2;
        int q = v & 3;

        if (b < B && __ldg(has_smpl + b) > 0) {
            // quarter range [s_abs, e_abs) in absolute float indices
            int base_b = b * per_batch;
            int s_abs = base_b + (q * per_batch) / 4;
            int e_abs = base_b + ((q + 1) * per_batch) / 4;

            int s4 = (s_abs + 3) & ~3;     // first f4-aligned float
            int e4 = e_abs & ~3;           // last f4-aligned float (exclusive)

            float lshape = 0.0f;

            // scalar head + tail (<=3 floats each) by thread 0
            if (threadIdx.x == 0) {
                for (int e = s_abs; e < s4 && e < e_abs; ++e)
                    lshape += fabsf(__ldg(pred_vertices + e) - __ldg(gt_vertices + e));
                if (e4 > s4)
                    for (int e = e4; e < e_abs; ++e)
                        lshape += fabsf(__ldg(pred_vertices + e) - __ldg(gt_vertices + e));
            }

            // aligned float4 body — pure streaming, no masking
            if (e4 > s4) {
                const float4* pv4 = reinterpret_cast<const float4*>(pred_vertices) + (s4 >> 2);
                const float4* gv4 = reinterpret_cast<const float4*>(gt_vertices) + (s4 >> 2);
                int n = (e4 - s4) >> 2;
                int i = threadIdx.x;
                for (; i + 3 * 256 < n; i += 4 * 256) {
                    float4 a0 = __ldg(pv4 + i);
                    float4 a1 = __ldg(pv4 + i + 256);
                    float4 a2 = __ldg(pv4 + i + 512);
                    float4 a3 = __ldg(pv4 + i + 768);
                    float4 c0 = __ldg(gv4 + i);
                    float4 c1 = __ldg(gv4 + i + 256);
                    float4 c2 = __ldg(gv4 + i + 512);
                    float4 c3 = __ldg(gv4 + i + 768);
                    lshape += fabsf(a0.x - c0.x) + fabsf(a0.y - c0.y)
                            + fabsf(a0.z - c0.z) + fabsf(a0.w - c0.w);
                    lshape += fabsf(a1.x - c1.x) + fabsf(a1.y - c1.y)
                            + fabsf(a1.z - c1.z) + fabsf(a1.w - c1.w);
                    lshape += fabsf(a2.x - c2.x) + fabsf(a2.y - c2.y)
                            + fabsf(a2.z - c2.z) + fabsf(a2.w - c2.w);
                    lshape += fabsf(a3.x - c3.x) + fabsf(a3.y - c3.y)
                            + fabsf(a3.z - c3.z) + fabsf(a3.w - c3.w);
                }
                for (; i < n; i += 256) {
                    float4 a = __ldg(pv4 + i);
                    float4 c = __ldg(gv4 + i);
                    lshape += fabsf(a.x - c.x) + fabsf(a.y - c.y)
                            + fabsf(a.z - c.z) + fabsf(a.w - c.w);
                }
            }

            block_reduce_add(lshape, &g_state.acc[0], sh);
        }
    } else {
        // ================= per-batch losses (warp per batch) =================
        int gw   = (blockIdx.x * blockDim.x + threadIdx.x) >> 5;
        int lane = threadIdx.x & 31;

        if (gw < B) {
            const int b = gw;
            const bool act = (lane < 24);

            float px = 0.f, py = 0.f, pz = 0.f;
            float gx = 0.f, gy = 0.f, gz = 0.f, c3 = 0.f;
            float g2x = 0.f, g2y = 0.f, c2 = 0.f;
            if (act) {
                const float* pj = pred_joints + ((size_t)b * 24 + lane) * 3;
                px = __ldg(pj + 0); py = __ldg(pj + 1); pz = __ldg(pj + 2);
                const float* gk = gt_kp3d + ((size_t)b * 24 + lane) * 4;
                gx = __ldg(gk + 0); gy = __ldg(gk + 1); gz = __ldg(gk + 2); c3 = __ldg(gk + 3);
                const float* g2 = gt_kp2d + ((size_t)b * 24 + lane) * 3;
                g2x = __ldg(g2 + 0); g2y = __ldg(g2 + 1); c2 = __ldg(g2 + 2);
            }
            float cam0 = __ldg(pred_camera + b * 3 + 0);
            float cam1 = __ldg(pred_camera + b * 3 + 1);
            float cam2 = __ldg(pred_camera + b * 3 + 2);
            float m = (__ldg(has_smpl + b) > 0) ? 1.0f : 0.0f;

            // ---- pose loss (masked, warp-uniform skip) ----
            float sp = 0.f;
            if (m != 0.0f) {
                const float4* pr4 = reinterpret_cast<const float4*>(pred_rotmat) + (size_t)b * 54;
                const float4* gr4 = reinterpret_cast<const float4*>(gt_rotmat)   + (size_t)b * 54;
                float4 a0 = __ldg(pr4 + lane);
                float4 b0 = __ldg(gr4 + lane);
                float4 a1, b1;
                bool second = (lane + 32 < 54);
                if (second) { a1 = __ldg(pr4 + lane + 32); b1 = __ldg(gr4 + lane + 32); }
                float d0 = a0.x - b0.x, d1 = a0.y - b0.y, d2 = a0.z - b0.z, d3 = a0.w - b0.w;
                sp = d0*d0 + d1*d1 + d2*d2 + d3*d3;
                if (second) {
                    float e0 = a1.x - b1.x, e1 = a1.y - b1.y, e2 = a1.z - b1.z, e3 = a1.w - b1.w;
                    sp += e0*e0 + e1*e1 + e2*e2 + e3*e3;
                }
            }
            sp = wsum(sp);

            // ---- kp2d ----
            float s2 = 0.f;
            {
                float depth = __fdividef(2.0f * F_LEN, EPSF + cam0 * IMG);
                if (act) {
                    float invz = __fdividef(1.0f, pz + depth);
                    float kx = (F_LEN * (px + cam1) * invz + IMG * 0.5f) * (1.0f / IMG);
                    float ky = (F_LEN * (py + cam2) * invz + IMG * 0.5f) * (1.0f / IMG);
                    s2 = c2 * (fabsf(kx - g2x * (1.0f / IMG)) +
                               fabsf(ky - g2y * (1.0f / IMG)));
                }
            }

            // ---- kp3d ----
            float ppx = 0.5f * (__shfl_sync(FM, px, 2) + __shfl_sync(FM, px, 3));
            float ppy = 0.5f * (__shfl_sync(FM, py, 2) + __shfl_sync(FM, py, 3));
            float ppz = 0.5f * (__shfl_sync(FM, pz, 2) + __shfl_sync(FM, pz, 3));
            float gpx = 0.5f * (__shfl_sync(FM, gx, 2) + __shfl_sync(FM, gx, 3));
            float gpy = 0.5f * (__shfl_sync(FM, gy, 2) + __shfl_sync(FM, gy, 3));
            float gpz = 0.5f * (__shfl_sync(FM, gz, 2) + __shfl_sync(FM, gz, 3));
            float s3 = 0.f;
            if (act) {
                s3 = c3 * (fabsf((px - ppx) - (gx - gpx)) +
                           fabsf((py - ppy) - (gy - gpy)) +
                           fabsf((pz - ppz) - (gz - gpz)));
            }
            float s23 = wsum(s2 * (1.0f / 48.0f) + s3 * (1.0f / 72.0f));

            // ---- betas ----
            float sb = 0.f;
            if (m != 0.0f && lane < 10) {
                float d = __ldg(pred_betas + b * 10 + lane) - __ldg(gt_shape + b * 10 + lane);
                sb = d * d;
            }
            sb = wsum(sb);

            // ---- Procrustes (fp32, per-warp) ----
            const float inv24 = 1.0f / 24.0f;
            float m1x = wsum(px) * inv24, m1y = wsum(py) * inv24, m1z = wsum(pz) * inv24;
            float m2x = wsum(gx) * inv24, m2y = wsum(gy) * inv24, m2z = wsum(gz) * inv24;

            float x1x = 0.f, x1y = 0.f, x1z = 0.f, x2x = 0.f, x2y = 0.f, x2z = 0.f;
            if (act) {
                x1x = px - m1x; x1y = py - m1y; x1z = pz - m1z;
                x2x = gx - m2x; x2y = gy - m2y; x2z = gz - m2z;
            }
            float var1 = wsum(x1x * x1x + x1y * x1y + x1z * x1z);

            float K[3][3];
            K[0][0] = wsum(x1x * x2x) + EPSF; K[0][1] = wsum(x1x * x2y) + EPSF; K[0][2] = wsum(x1x * x2z) + EPSF;
            K[1][0] = wsum(x1y * x2x) + EPSF; K[1][1] = wsum(x1y * x2y) + EPSF; K[1][2] = wsum(x1y * x2z) + EPSF;
            K[2][0] = wsum(x1z * x2x) + EPSF; K[2][1] = wsum(x1z * x2y) + EPSF; K[2][2] = wsum(x1z * x2z) + EPSF;

            float A[3][3];
            #pragma unroll
            for (int r = 0; r < 3; r++)
                #pragma unroll
                for (int c = 0; c < 3; c++)
                    A[r][c] = K[0][r] * K[0][c] + K[1][r] * K[1][c] + K[2][r] * K[2][c];

            float Vv[3][3] = {{1.f,0.f,0.f},{0.f,1.f,0.f},{0.f,0.f,1.f}};
            float nrm = A[0][0]*A[0][0] + A[1][1]*A[1][1] + A[2][2]*A[2][2];
            for (int sweep = 0; sweep < 8; ++sweep) {
                float off = A[0][1]*A[0][1] + A[0][2]*A[0][2] + A[1][2]*A[1][2];
                if (off <= 1e-14f * nrm) break;
                #pragma unroll
                for (int p = 0; p < 2; p++) {
                    #pragma unroll
                    for (int q = p + 1; q < 3; q++) {
                        float apq = A[p][q];
                        if (fabsf(apq) < 1e-30f) continue;
                        float theta = __fdividef(A[q][q] - A[p][p], 2.0f * apq);
                        float w1 = theta * theta + 1.0f;
                        float sq = w1 * rsqrtf(w1);
                        float t = __fdividef(1.0f, fabsf(theta) + sq);
                        if (theta < 0.0f) t = -t;
                        float c = rsqrtf(t * t + 1.0f);
                        float s = t * c;
                        float app = A[p][p], aqq = A[q][q];
                        A[p][p] = app - t * apq;
                        A[q][q] = aqq + t * apq;
                        A[p][q] = A[q][p] = 0.0f;
                        int k = 3 - p - q;
                        float akp = A[k][p], akq = A[k][q];
                        A[k][p] = A[p][k] = c * akp - s * akq;
                        A[k][q] = A[q][k] = s * akp + c * akq;
                        #pragma unroll
                        for (int r = 0; r < 3; r++) {
                            float vrp = Vv[r][p], vrq = Vv[r][q];
                            Vv[r][p] = c * vrp - s * vrq;
                            Vv[r][q] = s * vrp + c * vrq;
                        }
                    }
                }
            }
            float w[3] = {A[0][0], A[1][1], A[2][2]};
            #pragma unroll
            for (int i = 0; i < 2; i++) {
                int mx = i;
                #pragma unroll
                for (int j2 = 1; j2 < 3; j2++) if (j2 > i && w[j2] > w[mx]) mx = j2;
                if (mx != i) {
                    float tw = w[i]; w[i] = w[mx]; w[mx] = tw;
                    #pragma unroll
                    for (int r = 0; r < 3; r++) {
                        float tv = Vv[r][i]; Vv[r][i] = Vv[r][mx]; Vv[r][mx] = tv;
                    }
                }
            }

            float detK = K[0][0]*(K[1][1]*K[2][2] - K[1][2]*K[2][1])
                       - K[0][1]*(K[1][0]*K[2][2] - K[1][2]*K[2][0])
                       + K[0][2]*(K[1][0]*K[2][1] - K[1][1]*K[2][0]);
            float sgn = (detK > 0.f) ? 1.f : ((detK < 0.f) ? -1.f : 0.f);
            float z[3] = {1.f, 1.f, sgn};

            float R[3][3] = {{0,0,0},{0,0,0},{0,0,0}};
            #pragma unroll
            for (int i = 0; i < 3; i++) {
                float kv[3];
                #pragma unroll
                for (int r = 0; r < 3; r++)
                    kv[r] = K[r][0]*Vv[0][i] + K[r][1]*Vv[1][i] + K[r][2]*Vv[2][i];
                float f = z[i] * rsqrtf(fmaxf(w[i], 1e-30f));
                #pragma unroll
                for (int r = 0; r < 3; r++)
                    #pragma unroll
                    for (int c = 0; c < 3; c++)
                        R[r][c] += f * Vv[r][i] * kv[c];
            }
            float trRK = 0.f;
            #pragma unroll
            for (int r = 0; r < 3; r++)
                #pragma unroll
                for (int c = 0; c < 3; c++) trRK += R[r][c] * K[c][r];
            float scale = __fdividef(trRK, var1);

            float tx = m2x - scale * (R[0][0]*m1x + R[0][1]*m1y + R[0][2]*m1z);
            float ty = m2y - scale * (R[1][0]*m1x + R[1][1]*m1y + R[1][2]*m1z);
            float tz = m2z - scale * (R[2][0]*m1x + R[2][1]*m1y + R[2][2]*m1z);

            float err = 0.f;
            if (act) {
                float hx = scale * (R[0][0]*px + R[0][1]*py + R[0][2]*pz) + tx - gx;
                float hy = scale * (R[1][0]*px + R[1][1]*py + R[1][2]*pz) + ty - gy;
                float hz = scale * (R[2][0]*px + R[2][1]*py + R[2][2]*pz) + tz - gz;
                float hsq = hx*hx + hy*hy + hz*hz;
                err = (hsq > 0.f) ? hsq * rsqrtf(hsq) : 0.f;
            }
            err = wsum(err);

            if (lane == 0) {
                atomicAdd(&g_state.acc[4], (double)s23);
                atomicAdd(&g_state.acc[1], (double)sp);
                atomicAdd(&g_state.acc[2], (double)sb);
                atomicAdd(&g_state.acc[3], (double)m);
                atomicAdd(&g_state.acc[6], (double)err);
            }
        }
    }

    // ================= finalize: last block to arrive =================
    __syncthreads();
    __threadfence();
    if (threadIdx.x == 0) {
        unsigned old = atomicInc(&g_state.done, gridDim.x - 1);
        if (old == gridDim.x - 1) {
            __threadfence();
            volatile double* a = g_state.acc;
            double nv         = a[3];
            double loss_shape = a[0] / (nv * (double)V * 3.0 + EPSD);
            double loss_pose  = a[1] / (nv * 216.0 + EPSD);
            double loss_betas = a[2] / (nv * 10.0 + EPSD);
            double l23 = 4.0 * a[4] / (double)B;
            double pa  = a[6] / ((double)B * 24.0);
            out[0] = (float)(l23 + loss_shape + loss_pose + 0.01*loss_betas + pa);
            #pragma unroll
            for (int k = 0; k < 7; k++) g_state.acc[k] = 0.0;
        }
    }
}

// ---------------------------------------------------------------------------
extern "C" void kernel_launch(void* const* d_in, const int* in_sizes, int n_in,
                              void* d_out, int out_size)
{
    const float* pred_rotmat   = (const float*)d_in[0];
    const float* pred_camera   = (const float*)d_in[1];
    const float* pred_joints   = (const float*)d_in[2];
    const float* pred_betas    = (const float*)d_in[4];
    const float* pred_vertices = (const float*)d_in[3];
    const float* gt_rotmat     = (const float*)d_in[5];
    const float* gt_shape      = (const float*)d_in[6];
    const float* gt_kp2d       = (const float*)d_in[7];
    const float* gt_kp3d       = (const float*)d_in[8];
    const float* gt_vertices   = (const float*)d_in[9];
    const int*   has_smpl      = (const int*)d_in[10];

    int B = in_sizes[1] / 3;
    int ntot = in_sizes[3];
    int V = ntot / (B * 3);

    int batchBlocks = (B * 32 + 255) / 256;     // 64 for B=512
    int grid = batchBlocks + 4 * B;             // 4 vert blocks per batch

    fused_kernel<<<grid, 256>>>(pred_rotmat, pred_camera, pred_joints,
                                pred_vertices, pred_betas, gt_rotmat,
                                gt_shape, gt_kp2d, gt_kp3d, gt_vertices,
                                has_smpl, B, V, batchBlocks,
                                (float*)d_out);
}

// round 7
// speedup vs baseline: 1.3788x; 1.1212x over previous
#include <cuda_runtime.h>
#include <math.h>

#define F_LEN 1000.0f
#define IMG   512.0f
#define EPSF  1e-8f
#define EPSD  1e-8

// acc slots: 0 shape, 1 pose, 2 betas, 3 n_valid, 4 kp23(combined), 6 pa
// Zero at module load; finalize block re-zeroes acc+work after use.
__device__ struct {
    double acc[7];
    unsigned int done;
    unsigned int work;
} g_state;

__device__ __forceinline__ float wsum(float v) {
    #pragma unroll
    for (int o = 16; o; o >>= 1) v += __shfl_xor_sync(0xffffffffu, v, o);
    return v;
}

__device__ __forceinline__ void block_reduce_add(float local, double* slot,
                                                 double* sh)
{
    double v = (double)local;
    #pragma unroll
    for (int o = 16; o; o >>= 1) v += __shfl_down_sync(0xffffffffu, v, o);
    int lane = threadIdx.x & 31, wid = threadIdx.x >> 5;
    if (lane == 0) sh[wid] = v;
    __syncthreads();
    if (wid == 0) {
        int nw = blockDim.x >> 5;
        v = (lane < nw) ? sh[lane] : 0.0;
        #pragma unroll
        for (int o = 16; o; o >>= 1) v += __shfl_down_sync(0xffffffffu, v, o);
        if (lane == 0) atomicAdd(slot, v);
    }
}

// ---------------------------------------------------------------------------
__global__ __launch_bounds__(256, 5)
void fused_kernel(const float* __restrict__ pred_rotmat,
                  const float* __restrict__ pred_camera,
                  const float* __restrict__ pred_joints,
                  const float* __restrict__ pred_vertices,
                  const float* __restrict__ pred_betas,
                  const float* __restrict__ gt_rotmat,
                  const float* __restrict__ gt_shape,
                  const float* __restrict__ gt_kp2d,
                  const float* __restrict__ gt_kp3d,
                  const float* __restrict__ gt_vertices,
                  const int*   __restrict__ has_smpl,
                  int B, int V, int batchBlocks,
                  float* __restrict__ out)
{
    __shared__ double sh[32];
    __shared__ int sh_item;
    const unsigned FM = 0xffffffffu;
    const int per_batch = V * 3;

    if (blockIdx.x >= batchBlocks) {
        // ========== vertex L1: dynamic queue of (batch, half) items ==========
        const int totalItems = B * 2;
        float lshape = 0.0f;

        for (;;) {
            if (threadIdx.x == 0)
                sh_item = (int)atomicAdd(&g_state.work, 1u);
            __syncthreads();
            int item = sh_item;
            __syncthreads();
            if (item >= totalItems) break;

            int b = item >> 1;
            int h = item & 1;
            if (__ldg(has_smpl + b) <= 0) continue;

            // half range [s_abs, e_abs) in absolute float indices
            int base_b = b * per_batch;
            int s_abs = base_b + (h * per_batch) / 2;
            int e_abs = base_b + ((h + 1) * per_batch) / 2;

            int s4 = (s_abs + 3) & ~3;
            int e4 = e_abs & ~3;

            if (threadIdx.x == 0) {
                for (int e = s_abs; e < s4 && e < e_abs; ++e)
                    lshape += fabsf(__ldg(pred_vertices + e) - __ldg(gt_vertices + e));
                if (e4 > s4)
                    for (int e = e4; e < e_abs; ++e)
                        lshape += fabsf(__ldg(pred_vertices + e) - __ldg(gt_vertices + e));
            }

            if (e4 > s4) {
                const float4* pv4 = reinterpret_cast<const float4*>(pred_vertices) + (s4 >> 2);
                const float4* gv4 = reinterpret_cast<const float4*>(gt_vertices) + (s4 >> 2);
                int n = (e4 - s4) >> 2;
                int i = threadIdx.x;
                for (; i + 3 * 256 < n; i += 4 * 256) {
                    float4 a0 = __ldg(pv4 + i);
                    float4 a1 = __ldg(pv4 + i + 256);
                    float4 a2 = __ldg(pv4 + i + 512);
                    float4 a3 = __ldg(pv4 + i + 768);
                    float4 c0 = __ldg(gv4 + i);
                    float4 c1 = __ldg(gv4 + i + 256);
                    float4 c2 = __ldg(gv4 + i + 512);
                    float4 c3 = __ldg(gv4 + i + 768);
                    lshape += fabsf(a0.x - c0.x) + fabsf(a0.y - c0.y)
                            + fabsf(a0.z - c0.z) + fabsf(a0.w - c0.w);
                    lshape += fabsf(a1.x - c1.x) + fabsf(a1.y - c1.y)
                            + fabsf(a1.z - c1.z) + fabsf(a1.w - c1.w);
                    lshape += fabsf(a2.x - c2.x) + fabsf(a2.y - c2.y)
                            + fabsf(a2.z - c2.z) + fabsf(a2.w - c2.w);
                    lshape += fabsf(a3.x - c3.x) + fabsf(a3.y - c3.y)
                            + fabsf(a3.z - c3.z) + fabsf(a3.w - c3.w);
                }
                for (; i < n; i += 256) {
                    float4 a = __ldg(pv4 + i);
                    float4 c = __ldg(gv4 + i);
                    lshape += fabsf(a.x - c.x) + fabsf(a.y - c.y)
                            + fabsf(a.z - c.z) + fabsf(a.w - c.w);
                }
            }
        }

        block_reduce_add(lshape, &g_state.acc[0], sh);
    } else {
        // ================= per-batch losses (warp per batch) =================
        int gw   = (blockIdx.x * blockDim.x + threadIdx.x) >> 5;
        int lane = threadIdx.x & 31;

        if (gw < B) {
            const int b = gw;
            const bool act = (lane < 24);

            float px = 0.f, py = 0.f, pz = 0.f;
            float gx = 0.f, gy = 0.f, gz = 0.f, c3 = 0.f;
            float g2x = 0.f, g2y = 0.f, c2 = 0.f;
            if (act) {
                const float* pj = pred_joints + ((size_t)b * 24 + lane) * 3;
                px = __ldg(pj + 0); py = __ldg(pj + 1); pz = __ldg(pj + 2);
                const float* gk = gt_kp3d + ((size_t)b * 24 + lane) * 4;
                gx = __ldg(gk + 0); gy = __ldg(gk + 1); gz = __ldg(gk + 2); c3 = __ldg(gk + 3);
                const float* g2 = gt_kp2d + ((size_t)b * 24 + lane) * 3;
                g2x = __ldg(g2 + 0); g2y = __ldg(g2 + 1); c2 = __ldg(g2 + 2);
            }
            float cam0 = __ldg(pred_camera + b * 3 + 0);
            float cam1 = __ldg(pred_camera + b * 3 + 1);
            float cam2 = __ldg(pred_camera + b * 3 + 2);
            float m = (__ldg(has_smpl + b) > 0) ? 1.0f : 0.0f;

            // ---- pose loss (masked, warp-uniform skip) ----
            float sp = 0.f;
            if (m != 0.0f) {
                const float4* pr4 = reinterpret_cast<const float4*>(pred_rotmat) + (size_t)b * 54;
                const float4* gr4 = reinterpret_cast<const float4*>(gt_rotmat)   + (size_t)b * 54;
                float4 a0 = __ldg(pr4 + lane);
                float4 b0 = __ldg(gr4 + lane);
                float4 a1, b1;
                bool second = (lane + 32 < 54);
                if (second) { a1 = __ldg(pr4 + lane + 32); b1 = __ldg(gr4 + lane + 32); }
                float d0 = a0.x - b0.x, d1 = a0.y - b0.y, d2 = a0.z - b0.z, d3 = a0.w - b0.w;
                sp = d0*d0 + d1*d1 + d2*d2 + d3*d3;
                if (second) {
                    float e0 = a1.x - b1.x, e1 = a1.y - b1.y, e2 = a1.z - b1.z, e3 = a1.w - b1.w;
                    sp += e0*e0 + e1*e1 + e2*e2 + e3*e3;
                }
            }
            sp = wsum(sp);

            // ---- kp2d ----
            float s2 = 0.f;
            {
                float depth = __fdividef(2.0f * F_LEN, EPSF + cam0 * IMG);
                if (act) {
                    float invz = __fdividef(1.0f, pz + depth);
                    float kx = (F_LEN * (px + cam1) * invz + IMG * 0.5f) * (1.0f / IMG);
                    float ky = (F_LEN * (py + cam2) * invz + IMG * 0.5f) * (1.0f / IMG);
                    s2 = c2 * (fabsf(kx - g2x * (1.0f / IMG)) +
                               fabsf(ky - g2y * (1.0f / IMG)));
                }
            }

            // ---- kp3d ----
            float ppx = 0.5f * (__shfl_sync(FM, px, 2) + __shfl_sync(FM, px, 3));
            float ppy = 0.5f * (__shfl_sync(FM, py, 2) + __shfl_sync(FM, py, 3));
            float ppz = 0.5f * (__shfl_sync(FM, pz, 2) + __shfl_sync(FM, pz, 3));
            float gpx = 0.5f * (__shfl_sync(FM, gx, 2) + __shfl_sync(FM, gx, 3));
            float gpy = 0.5f * (__shfl_sync(FM, gy, 2) + __shfl_sync(FM, gy, 3));
            float gpz = 0.5f * (__shfl_sync(FM, gz, 2) + __shfl_sync(FM, gz, 3));
            float s3 = 0.f;
            if (act) {
                s3 = c3 * (fabsf((px - ppx) - (gx - gpx)) +
                           fabsf((py - ppy) - (gy - gpy)) +
                           fabsf((pz - ppz) - (gz - gpz)));
            }
            float s23 = wsum(s2 * (1.0f / 48.0f) + s3 * (1.0f / 72.0f));

            // ---- betas ----
            float sb = 0.f;
            if (m != 0.0f && lane < 10) {
                float d = __ldg(pred_betas + b * 10 + lane) - __ldg(gt_shape + b * 10 + lane);
                sb = d * d;
            }
            sb = wsum(sb);

            // ---- Procrustes (fp32, per-warp) ----
            const float inv24 = 1.0f / 24.0f;
            float m1x = wsum(px) * inv24, m1y = wsum(py) * inv24, m1z = wsum(pz) * inv24;
            float m2x = wsum(gx) * inv24, m2y = wsum(gy) * inv24, m2z = wsum(gz) * inv24;

            float x1x = 0.f, x1y = 0.f, x1z = 0.f, x2x = 0.f, x2y = 0.f, x2z = 0.f;
            if (act) {
                x1x = px - m1x; x1y = py - m1y; x1z = pz - m1z;
                x2x = gx - m2x; x2y = gy - m2y; x2z = gz - m2z;
            }
            float var1 = wsum(x1x * x1x + x1y * x1y + x1z * x1z);

            float K[3][3];
            K[0][0] = wsum(x1x * x2x) + EPSF; K[0][1] = wsum(x1x * x2y) + EPSF; K[0][2] = wsum(x1x * x2z) + EPSF;
            K[1][0] = wsum(x1y * x2x) + EPSF; K[1][1] = wsum(x1y * x2y) + EPSF; K[1][2] = wsum(x1y * x2z) + EPSF;
            K[2][0] = wsum(x1z * x2x) + EPSF; K[2][1] = wsum(x1z * x2y) + EPSF; K[2][2] = wsum(x1z * x2z) + EPSF;

            float A[3][3];
            #pragma unroll
            for (int r = 0; r < 3; r++)
                #pragma unroll
                for (int c = 0; c < 3; c++)
                    A[r][c] = K[0][r] * K[0][c] + K[1][r] * K[1][c] + K[2][r] * K[2][c];

            float Vv[3][3] = {{1.f,0.f,0.f},{0.f,1.f,0.f},{0.f,0.f,1.f}};
            float nrm = A[0][0]*A[0][0] + A[1][1]*A[1][1] + A[2][2]*A[2][2];
            for (int sweep = 0; sweep < 8; ++sweep) {
                float off = A[0][1]*A[0][1] + A[0][2]*A[0][2] + A[1][2]*A[1][2];
                if (off <= 1e-14f * nrm) break;
                #pragma unroll
                for (int p = 0; p < 2; p++) {
                    #pragma unroll
                    for (int q = p + 1; q < 3; q++) {
                        float apq = A[p][q];
                        if (fabsf(apq) < 1e-30f) continue;
                        float theta = __fdividef(A[q][q] - A[p][p], 2.0f * apq);
                        float w1 = theta * theta + 1.0f;
                        float sq = w1 * rsqrtf(w1);
                        float t = __fdividef(1.0f, fabsf(theta) + sq);
                        if (theta < 0.0f) t = -t;
                        float c = rsqrtf(t * t + 1.0f);
                        float s = t * c;
                        float app = A[p][p], aqq = A[q][q];
                        A[p][p] = app - t * apq;
                        A[q][q] = aqq + t * apq;
                        A[p][q] = A[q][p] = 0.0f;
                        int k = 3 - p - q;
                        float akp = A[k][p], akq = A[k][q];
                        A[k][p] = A[p][k] = c * akp - s * akq;
                        A[k][q] = A[q][k] = s * akp + c * akq;
                        #pragma unroll
                        for (int r = 0; r < 3; r++) {
                            float vrp = Vv[r][p], vrq = Vv[r][q];
                            Vv[r][p] = c * vrp - s * vrq;
                            Vv[r][q] = s * vrp + c * vrq;
                        }
                    }
                }
            }
            float w[3] = {A[0][0], A[1][1], A[2][2]};
            #pragma unroll
            for (int i = 0; i < 2; i++) {
                int mx = i;
                #pragma unroll
                for (int j2 = 1; j2 < 3; j2++) if (j2 > i && w[j2] > w[mx]) mx = j2;
                if (mx != i) {
                    float tw = w[i]; w[i] = w[mx]; w[mx] = tw;
                    #pragma unroll
                    for (int r = 0; r < 3; r++) {
                        float tv = Vv[r][i]; Vv[r][i] = Vv[r][mx]; Vv[r][mx] = tv;
                    }
                }
            }

            float detK = K[0][0]*(K[1][1]*K[2][2] - K[1][2]*K[2][1])
                       - K[0][1]*(K[1][0]*K[2][2] - K[1][2]*K[2][0])
                       + K[0][2]*(K[1][0]*K[2][1] - K[1][1]*K[2][0]);
            float sgn = (detK > 0.f) ? 1.f : ((detK < 0.f) ? -1.f : 0.f);
            float z[3] = {1.f, 1.f, sgn};

            float R[3][3] = {{0,0,0},{0,0,0},{0,0,0}};
            #pragma unroll
            for (int i = 0; i < 3; i++) {
                float kv[3];
                #pragma unroll
                for (int r = 0; r < 3; r++)
                    kv[r] = K[r][0]*Vv[0][i] + K[r][1]*Vv[1][i] + K[r][2]*Vv[2][i];
                float f = z[i] * rsqrtf(fmaxf(w[i], 1e-30f));
                #pragma unroll
                for (int r = 0; r < 3; r++)
                    #pragma unroll
                    for (int c = 0; c < 3; c++)
                        R[r][c] += f * Vv[r][i] * kv[c];
            }
            float trRK = 0.f;
            #pragma unroll
            for (int r = 0; r < 3; r++)
                #pragma unroll
                for (int c = 0; c < 3; c++) trRK += R[r][c] * K[c][r];
            float scale = __fdividef(trRK, var1);

            float tx = m2x - scale * (R[0][0]*m1x + R[0][1]*m1y + R[0][2]*m1z);
            float ty = m2y - scale * (R[1][0]*m1x + R[1][1]*m1y + R[1][2]*m1z);
            float tz = m2z - scale * (R[2][0]*m1x + R[2][1]*m1y + R[2][2]*m1z);

            float err = 0.f;
            if (act) {
                float hx = scale * (R[0][0]*px + R[0][1]*py + R[0][2]*pz) + tx - gx;
                float hy = scale * (R[1][0]*px + R[1][1]*py + R[1][2]*pz) + ty - gy;
                float hz = scale * (R[2][0]*px + R[2][1]*py + R[2][2]*pz) + tz - gz;
                float hsq = hx*hx + hy*hy + hz*hz;
                err = (hsq > 0.f) ? hsq * rsqrtf(hsq) : 0.f;
            }
            err = wsum(err);

            if (lane == 0) {
                atomicAdd(&g_state.acc[4], (double)s23);
                atomicAdd(&g_state.acc[1], (double)sp);
                atomicAdd(&g_state.acc[2], (double)sb);
                atomicAdd(&g_state.acc[3], (double)m);
                atomicAdd(&g_state.acc[6], (double)err);
            }
        }
    }

    // ================= finalize: last block to arrive =================
    __syncthreads();
    __threadfence();
    if (threadIdx.x == 0) {
        unsigned old = atomicInc(&g_state.done, gridDim.x - 1);
        if (old == gridDim.x - 1) {
            __threadfence();
            volatile double* a = g_state.acc;
            double nv         = a[3];
            double loss_shape = a[0] / (nv * (double)V * 3.0 + EPSD);
            double loss_pose  = a[1] / (nv * 216.0 + EPSD);
            double loss_betas = a[2] / (nv * 10.0 + EPSD);
            double l23 = 4.0 * a[4] / (double)B;
            double pa  = a[6] / ((double)B * 24.0);
            out[0] = (float)(l23 + loss_shape + loss_pose + 0.01*loss_betas + pa);
            #pragma unroll
            for (int k = 0; k < 7; k++) g_state.acc[k] = 0.0;
            g_state.work = 0u;    // reset work queue for next graph replay
        }
    }
}

// ---------------------------------------------------------------------------
extern "C" void kernel_launch(void* const* d_in, const int* in_sizes, int n_in,
                              void* d_out, int out_size)
{
    const float* pred_rotmat   = (const float*)d_in[0];
    const float* pred_camera   = (const float*)d_in[1];
    const float* pred_joints   = (const float*)d_in[2];
    const float* pred_vertices = (const float*)d_in[3];
    const float* pred_betas    = (const float*)d_in[4];
    const float* gt_rotmat     = (const float*)d_in[5];
    const float* gt_shape      = (const float*)d_in[6];
    const float* gt_kp2d       = (const float*)d_in[7];
    const float* gt_kp3d       = (const float*)d_in[8];
    const float* gt_vertices   = (const float*)d_in[9];
    const int*   has_smpl      = (const int*)d_in[10];

    int B = in_sizes[1] / 3;
    int ntot = in_sizes[3];
    int V = ntot / (B * 3);

    int batchBlocks = (B * 32 + 255) / 256;     // 64 for B=512
    int grid = 148 * 5;                          // exactly one wave (740)
    if (grid <= batchBlocks) grid = batchBlocks + 148;

    fused_kernel<<<grid, 256>>>(pred_rotmat, pred_camera, pred_joints,
                                pred_vertices, pred_betas, gt_rotmat,
                                gt_shape, gt_kp2d, gt_kp3d, gt_vertices,
                                has_smpl, B, V, batchBlocks,
                                (float*)d_out);
}